// round 8
// baseline (speedup 1.0000x reference)
#include <cuda_runtime.h>
#include <math.h>

#define DIM   4096
#define CAP   8192
#define TOPK  8
#define NV4   (DIM / 4)          // 1024 float4 per row
#define RESIDENT_ROWS 3584       // 56 MiB of mb kept L2-resident (+64 MiB W = 120 < 126 MB)

// Scratch (no allocations allowed in kernel_launch).
__device__ float g_weighted[CAP];
__device__ int   g_topidx[TOPK];
__device__ float g_retrieved[DIM];

// ---------------------------------------------------------------------------
// Kernel 1: fused score pass, 2 rows/block.
// Rows < RESIDENT_ROWS: default-cached loads -> stay L2-resident across graph
// replays. Rows >= RESIDENT_ROWS: __ldcs evict-first stream (72 MiB DRAM).
// Block->row-pair map is a stride-7 bijection so L2-fed and DRAM-fed blocks
// interleave within each wave (L2 bandwidth adds on top of the DRAM stream).
// ---------------------------------------------------------------------------
__global__ __launch_bounds__(256) void score_kernel(
    const float* __restrict__ q,
    const float* __restrict__ mb,
    const float* __restrict__ imp,
    const float* __restrict__ age)
{
    const int p   = (int)((blockIdx.x * 7u) & 4095u);   // bijection on [0,4096)
    const int r0  = p * 2;
    const int r1  = r0 + 1;
    const int tid = threadIdx.x;
    const float4* m0 = reinterpret_cast<const float4*>(mb) + (size_t)r0 * NV4;
    const float4* m1 = reinterpret_cast<const float4*>(mb) + (size_t)r1 * NV4;
    const float4* qv = reinterpret_cast<const float4*>(q);

    float d0 = 0.f, n0 = 0.f, d1 = 0.f, n1 = 0.f, qn = 0.f;

    if (r0 < RESIDENT_ROWS) {
        // L2-resident slice: default policy keeps these lines hot across replays
        #pragma unroll
        for (int u = 0; u < 4; u++) {
            int i = tid + u * 256;
            float4 a0 = __ldg(&m0[i]);
            float4 a1 = __ldg(&m1[i]);
            float4 b  = qv[i];
            d0 += a0.x * b.x + a0.y * b.y + a0.z * b.z + a0.w * b.w;
            n0 += a0.x * a0.x + a0.y * a0.y + a0.z * a0.z + a0.w * a0.w;
            d1 += a1.x * b.x + a1.y * b.y + a1.z * b.z + a1.w * b.w;
            n1 += a1.x * a1.x + a1.y * a1.y + a1.z * a1.z + a1.w * a1.w;
            qn += b.x * b.x + b.y * b.y + b.z * b.z + b.w * b.w;
        }
    } else {
        // Streamed slice: evict-first, never pollutes W_dec / resident mb
        #pragma unroll
        for (int u = 0; u < 4; u++) {
            int i = tid + u * 256;
            float4 a0 = __ldcs(&m0[i]);
            float4 a1 = __ldcs(&m1[i]);
            float4 b  = qv[i];
            d0 += a0.x * b.x + a0.y * b.y + a0.z * b.z + a0.w * b.w;
            n0 += a0.x * a0.x + a0.y * a0.y + a0.z * a0.z + a0.w * a0.w;
            d1 += a1.x * b.x + a1.y * b.y + a1.z * b.z + a1.w * b.w;
            n1 += a1.x * a1.x + a1.y * a1.y + a1.z * a1.z + a1.w * a1.w;
            qn += b.x * b.x + b.y * b.y + b.z * b.z + b.w * b.w;
        }
    }

    #pragma unroll
    for (int o = 16; o > 0; o >>= 1) {
        d0 += __shfl_down_sync(0xffffffffu, d0, o);
        n0 += __shfl_down_sync(0xffffffffu, n0, o);
        d1 += __shfl_down_sync(0xffffffffu, d1, o);
        n1 += __shfl_down_sync(0xffffffffu, n1, o);
        qn += __shfl_down_sync(0xffffffffu, qn, o);
    }

    __shared__ float s0[8], s1[8], s2[8], s3[8], s4[8];
    const int w = tid >> 5;
    if ((tid & 31) == 0) { s0[w] = d0; s1[w] = n0; s2[w] = d1; s3[w] = n1; s4[w] = qn; }
    __syncthreads();

    if (tid == 0) {
        float D0 = 0.f, N0 = 0.f, D1 = 0.f, N1 = 0.f, Q = 0.f;
        #pragma unroll
        for (int i = 0; i < 8; i++) {
            D0 += s0[i]; N0 += s1[i]; D1 += s2[i]; N1 += s3[i]; Q += s4[i];
        }
        float qs = sqrtf(Q);
        float sim0 = D0 / fmaxf(qs * sqrtf(N0), 1e-8f);
        float sim1 = D1 / fmaxf(qs * sqrtf(N1), 1e-8f);
        g_weighted[r0] = sim0 * imp[r0] * expf(-0.001f * age[r0]);
        g_weighted[r1] = sim1 * imp[r1] * expf(-0.001f * age[r1]);
    }
}

// ---------------------------------------------------------------------------
// Kernel 2: top-8 of 8192 + gather/mean, fused. Single block of 1024 threads.
// ---------------------------------------------------------------------------
__global__ __launch_bounds__(1024) void topk_gather_kernel(const float* __restrict__ mb)
{
    __shared__ float w[CAP];          // 32 KB
    __shared__ float bv[32];
    __shared__ int   bi[32];
    __shared__ int   s_idx[TOPK];

    const int tid = threadIdx.x;
    for (int i = tid; i < CAP; i += 1024) w[i] = g_weighted[i];
    __syncthreads();

    for (int k = 0; k < TOPK; k++) {
        float best = -3.0e38f;
        int   idx  = -1;
        #pragma unroll
        for (int i = tid; i < CAP; i += 1024) {
            float v = w[i];
            if (v > best) { best = v; idx = i; }   // strict > keeps min index on ties
        }
        #pragma unroll
        for (int o = 16; o > 0; o >>= 1) {
            float ov = __shfl_down_sync(0xffffffffu, best, o);
            int   oi = __shfl_down_sync(0xffffffffu, idx, o);
            if (ov > best || (ov == best && oi < idx)) { best = ov; idx = oi; }
        }
        if ((tid & 31) == 0) { bv[tid >> 5] = best; bi[tid >> 5] = idx; }
        __syncthreads();
        if (tid == 0) {
            float bb = bv[0]; int ii = bi[0];
            #pragma unroll
            for (int j = 1; j < 32; j++)
                if (bv[j] > bb || (bv[j] == bb && bi[j] < ii)) { bb = bv[j]; ii = bi[j]; }
            s_idx[k] = ii;
            g_topidx[k] = ii;
            w[ii] = -3.0e38f;           // exclude from next pass
        }
        __syncthreads();
    }

    // gather: retrieved = mean of the 8 selected rows (1 float4 per thread)
    const float4* mbv = reinterpret_cast<const float4*>(mb);
    const int j = tid;                  // 0..1023 float4 lanes
    float4 acc = make_float4(0.f, 0.f, 0.f, 0.f);
    #pragma unroll
    for (int t = 0; t < TOPK; t++) {
        float4 x = __ldg(&mbv[(size_t)s_idx[t] * NV4 + j]);
        acc.x += x.x; acc.y += x.y; acc.z += x.z; acc.w += x.w;
    }
    reinterpret_cast<float4*>(g_retrieved)[j] =
        make_float4(acc.x * 0.125f, acc.y * 0.125f, acc.z * 0.125f, acc.w * 0.125f);
}

// ---------------------------------------------------------------------------
// Kernel 3: decode GEMV, 2 rows/block. W_dec default-cached -> L2-resident
// across graph replays (both mb streams are policy-contained).
// ---------------------------------------------------------------------------
__global__ __launch_bounds__(256) void gemv_kernel(
    const float* __restrict__ W,
    const float* __restrict__ b,
    float* __restrict__ out)
{
    const int r0  = blockIdx.x * 2;
    const int r1  = r0 + 1;
    const int tid = threadIdx.x;
    const float4* w0 = reinterpret_cast<const float4*>(W) + (size_t)r0 * NV4;
    const float4* w1 = reinterpret_cast<const float4*>(W) + (size_t)r1 * NV4;
    const float4* rv = reinterpret_cast<const float4*>(g_retrieved);

    float a0 = 0.f, a1 = 0.f;
    #pragma unroll
    for (int u = 0; u < 4; u++) {
        int i = tid + u * 256;
        float4 x0 = __ldg(&w0[i]);
        float4 x1 = __ldg(&w1[i]);
        float4 v  = rv[i];
        a0 += x0.x * v.x + x0.y * v.y + x0.z * v.z + x0.w * v.w;
        a1 += x1.x * v.x + x1.y * v.y + x1.z * v.z + x1.w * v.w;
    }
    #pragma unroll
    for (int o = 16; o > 0; o >>= 1) {
        a0 += __shfl_down_sync(0xffffffffu, a0, o);
        a1 += __shfl_down_sync(0xffffffffu, a1, o);
    }

    __shared__ float sa[8], sb[8];
    const int w = tid >> 5;
    if ((tid & 31) == 0) { sa[w] = a0; sb[w] = a1; }
    __syncthreads();
    if (tid == 0) {
        float t0 = 0.f, t1 = 0.f;
        #pragma unroll
        for (int i = 0; i < 8; i++) { t0 += sa[i]; t1 += sb[i]; }
        out[r0] = t0 + b[r0];
        out[r1] = t1 + b[r1];
    }
}

// ---------------------------------------------------------------------------
extern "C" void kernel_launch(void* const* d_in, const int* in_sizes, int n_in,
                              void* d_out, int out_size)
{
    const float* q   = (const float*)d_in[0];  // [4096]
    const float* mb  = (const float*)d_in[1];  // [8192, 4096]
    const float* imp = (const float*)d_in[2];  // [8192]
    const float* age = (const float*)d_in[3];  // [8192]
    const float* W   = (const float*)d_in[4];  // [4096, 4096]
    const float* b   = (const float*)d_in[5];  // [4096]
    float* out = (float*)d_out;                // [4096]

    score_kernel<<<CAP / 2, 256>>>(q, mb, imp, age);
    topk_gather_kernel<<<1, 1024>>>(mb);
    gemv_kernel<<<DIM / 2, 256>>>(W, b, out);
}

// round 9
// speedup vs baseline: 1.1404x; 1.1404x over previous
#include <cuda_runtime.h>
#include <math.h>

#define DIM   4096
#define CAP   8192
#define TOPK  8
#define NV4   (DIM / 4)          // 1024 float4 per row

// Scratch (no allocations allowed in kernel_launch).
__device__ float g_weighted[CAP];
__device__ int   g_topidx[TOPK];
__device__ float g_retrieved[DIM];

// ---------------------------------------------------------------------------
// Kernel 1: fused score pass, 2 rows/block, ALL __ldcs (evict-first: mb must
// never evict W_dec from L2). Block->row-pair map is a stride-7 bijection:
// measured +7% DRAM bandwidth vs linear mapping (R8).
// ---------------------------------------------------------------------------
__global__ __launch_bounds__(256) void score_kernel(
    const float* __restrict__ q,
    const float* __restrict__ mb,
    const float* __restrict__ imp,
    const float* __restrict__ age)
{
    const int p   = (int)((blockIdx.x * 7u) & 4095u);   // bijection on [0,4096)
    const int r0  = p * 2;
    const int r1  = r0 + 1;
    const int tid = threadIdx.x;
    const float4* m0 = reinterpret_cast<const float4*>(mb) + (size_t)r0 * NV4;
    const float4* m1 = reinterpret_cast<const float4*>(mb) + (size_t)r1 * NV4;
    const float4* qv = reinterpret_cast<const float4*>(q);

    float d0 = 0.f, n0 = 0.f, d1 = 0.f, n1 = 0.f, qn = 0.f;
    #pragma unroll
    for (int u = 0; u < 4; u++) {
        int i = tid + u * 256;
        float4 a0 = __ldcs(&m0[i]);
        float4 a1 = __ldcs(&m1[i]);
        float4 b  = qv[i];
        d0 += a0.x * b.x + a0.y * b.y + a0.z * b.z + a0.w * b.w;
        n0 += a0.x * a0.x + a0.y * a0.y + a0.z * a0.z + a0.w * a0.w;
        d1 += a1.x * b.x + a1.y * b.y + a1.z * b.z + a1.w * b.w;
        n1 += a1.x * a1.x + a1.y * a1.y + a1.z * a1.z + a1.w * a1.w;
        qn += b.x * b.x + b.y * b.y + b.z * b.z + b.w * b.w;
    }

    #pragma unroll
    for (int o = 16; o > 0; o >>= 1) {
        d0 += __shfl_down_sync(0xffffffffu, d0, o);
        n0 += __shfl_down_sync(0xffffffffu, n0, o);
        d1 += __shfl_down_sync(0xffffffffu, d1, o);
        n1 += __shfl_down_sync(0xffffffffu, n1, o);
        qn += __shfl_down_sync(0xffffffffu, qn, o);
    }

    __shared__ float s0[8], s1[8], s2[8], s3[8], s4[8];
    const int w = tid >> 5;
    if ((tid & 31) == 0) { s0[w] = d0; s1[w] = n0; s2[w] = d1; s3[w] = n1; s4[w] = qn; }
    __syncthreads();

    if (tid == 0) {
        float D0 = 0.f, N0 = 0.f, D1 = 0.f, N1 = 0.f, Q = 0.f;
        #pragma unroll
        for (int i = 0; i < 8; i++) {
            D0 += s0[i]; N0 += s1[i]; D1 += s2[i]; N1 += s3[i]; Q += s4[i];
        }
        float qs = sqrtf(Q);
        float sim0 = D0 / fmaxf(qs * sqrtf(N0), 1e-8f);
        float sim1 = D1 / fmaxf(qs * sqrtf(N1), 1e-8f);
        g_weighted[r0] = sim0 * imp[r0] * expf(-0.001f * age[r0]);
        g_weighted[r1] = sim1 * imp[r1] * expf(-0.001f * age[r1]);
    }
}

// ---------------------------------------------------------------------------
// Kernel 2: top-8 of 8192 + gather/mean, fused. Single block of 1024 threads.
// ---------------------------------------------------------------------------
__global__ __launch_bounds__(1024) void topk_gather_kernel(const float* __restrict__ mb)
{
    __shared__ float w[CAP];          // 32 KB
    __shared__ float bv[32];
    __shared__ int   bi[32];
    __shared__ int   s_idx[TOPK];

    const int tid = threadIdx.x;
    for (int i = tid; i < CAP; i += 1024) w[i] = g_weighted[i];
    __syncthreads();

    for (int k = 0; k < TOPK; k++) {
        float best = -3.0e38f;
        int   idx  = -1;
        #pragma unroll
        for (int i = tid; i < CAP; i += 1024) {
            float v = w[i];
            if (v > best) { best = v; idx = i; }   // strict > keeps min index on ties
        }
        #pragma unroll
        for (int o = 16; o > 0; o >>= 1) {
            float ov = __shfl_down_sync(0xffffffffu, best, o);
            int   oi = __shfl_down_sync(0xffffffffu, idx, o);
            if (ov > best || (ov == best && oi < idx)) { best = ov; idx = oi; }
        }
        if ((tid & 31) == 0) { bv[tid >> 5] = best; bi[tid >> 5] = idx; }
        __syncthreads();
        if (tid == 0) {
            float bb = bv[0]; int ii = bi[0];
            #pragma unroll
            for (int j = 1; j < 32; j++)
                if (bv[j] > bb || (bv[j] == bb && bi[j] < ii)) { bb = bv[j]; ii = bi[j]; }
            s_idx[k] = ii;
            g_topidx[k] = ii;
            w[ii] = -3.0e38f;           // exclude from next pass
        }
        __syncthreads();
    }

    // gather: retrieved = mean of the 8 selected rows (1 float4 per thread)
    const float4* mbv = reinterpret_cast<const float4*>(mb);
    const int j = tid;                  // 0..1023 float4 lanes
    float4 acc = make_float4(0.f, 0.f, 0.f, 0.f);
    #pragma unroll
    for (int t = 0; t < TOPK; t++) {
        float4 x = __ldg(&mbv[(size_t)s_idx[t] * NV4 + j]);
        acc.x += x.x; acc.y += x.y; acc.z += x.z; acc.w += x.w;
    }
    reinterpret_cast<float4*>(g_retrieved)[j] =
        make_float4(acc.x * 0.125f, acc.y * 0.125f, acc.z * 0.125f, acc.w * 0.125f);
}

// ---------------------------------------------------------------------------
// Kernel 3: decode GEMV, 2 rows/block. W_dec default-cached -> L2-resident
// across graph replays (mb stream is ldcs so it cannot evict W).
// ---------------------------------------------------------------------------
__global__ __launch_bounds__(256) void gemv_kernel(
    const float* __restrict__ W,
    const float* __restrict__ b,
    float* __restrict__ out)
{
    const int r0  = blockIdx.x * 2;
    const int r1  = r0 + 1;
    const int tid = threadIdx.x;
    const float4* w0 = reinterpret_cast<const float4*>(W) + (size_t)r0 * NV4;
    const float4* w1 = reinterpret_cast<const float4*>(W) + (size_t)r1 * NV4;
    const float4* rv = reinterpret_cast<const float4*>(g_retrieved);

    float a0 = 0.f, a1 = 0.f;
    #pragma unroll
    for (int u = 0; u < 4; u++) {
        int i = tid + u * 256;
        float4 x0 = __ldg(&w0[i]);
        float4 x1 = __ldg(&w1[i]);
        float4 v  = rv[i];
        a0 += x0.x * v.x + x0.y * v.y + x0.z * v.z + x0.w * v.w;
        a1 += x1.x * v.x + x1.y * v.y + x1.z * v.z + x1.w * v.w;
    }
    #pragma unroll
    for (int o = 16; o > 0; o >>= 1) {
        a0 += __shfl_down_sync(0xffffffffu, a0, o);
        a1 += __shfl_down_sync(0xffffffffu, a1, o);
    }

    __shared__ float sa[8], sb[8];
    const int w = tid >> 5;
    if ((tid & 31) == 0) { sa[w] = a0; sb[w] = a1; }
    __syncthreads();
    if (tid == 0) {
        float t0 = 0.f, t1 = 0.f;
        #pragma unroll
        for (int i = 0; i < 8; i++) { t0 += sa[i]; t1 += sb[i]; }
        out[r0] = t0 + b[r0];
        out[r1] = t1 + b[r1];
    }
}

// ---------------------------------------------------------------------------
extern "C" void kernel_launch(void* const* d_in, const int* in_sizes, int n_in,
                              void* d_out, int out_size)
{
    const float* q   = (const float*)d_in[0];  // [4096]
    const float* mb  = (const float*)d_in[1];  // [8192, 4096]
    const float* imp = (const float*)d_in[2];  // [8192]
    const float* age = (const float*)d_in[3];  // [8192]
    const float* W   = (const float*)d_in[4];  // [4096, 4096]
    const float* b   = (const float*)d_in[5];  // [4096]
    float* out = (float*)d_out;                // [4096]

    score_kernel<<<CAP / 2, 256>>>(q, mb, imp, age);
    topk_gather_kernel<<<1, 1024>>>(mb);
    gemv_kernel<<<DIM / 2, 256>>>(W, b, out);
}

// round 11
// speedup vs baseline: 1.1413x; 1.0007x over previous
#include <cuda_runtime.h>
#include <math.h>

#define DIM   4096
#define CAP   8192
#define TOPK  8
#define NV4   (DIM / 4)          // 1024 float4 per row
#define RES_PAIRS 768            // 1536 rows = 24 MiB resident (+64 MiB W = 88 MiB << L2)

// Scratch (no allocations allowed in kernel_launch).
__device__ float g_weighted[CAP];
__device__ int   g_topidx[TOPK];
__device__ float g_retrieved[DIM];

// ---------------------------------------------------------------------------
// Kernel 1: fused score pass, 2 rows/block, stride-7 permuted block->row map
// (measured +7% DRAM bw). Row-pairs p < RES_PAIRS (24 MiB) use default-cached
// loads -> L2-resident across graph replays; the rest are __ldcs evict-first
// so they never evict W_dec or the resident slice. Total resident demand
// 88 MiB, well under the ~120 MiB thrash point measured in R8.
// ---------------------------------------------------------------------------
__global__ __launch_bounds__(256) void score_kernel(
    const float* __restrict__ q,
    const float* __restrict__ mb,
    const float* __restrict__ imp,
    const float* __restrict__ age)
{
    const int p   = (int)((blockIdx.x * 7u) & 4095u);   // bijection on [0,4096)
    const int r0  = p * 2;
    const int r1  = r0 + 1;
    const int tid = threadIdx.x;
    const float4* m0 = reinterpret_cast<const float4*>(mb) + (size_t)r0 * NV4;
    const float4* m1 = reinterpret_cast<const float4*>(mb) + (size_t)r1 * NV4;
    const float4* qv = reinterpret_cast<const float4*>(q);

    float d0 = 0.f, n0 = 0.f, d1 = 0.f, n1 = 0.f, qn = 0.f;

    if (p < RES_PAIRS) {
        #pragma unroll
        for (int u = 0; u < 4; u++) {
            int i = tid + u * 256;
            float4 a0 = __ldg(&m0[i]);     // L2-resident slice
            float4 a1 = __ldg(&m1[i]);
            float4 b  = qv[i];
            d0 += a0.x * b.x + a0.y * b.y + a0.z * b.z + a0.w * b.w;
            n0 += a0.x * a0.x + a0.y * a0.y + a0.z * a0.z + a0.w * a0.w;
            d1 += a1.x * b.x + a1.y * b.y + a1.z * b.z + a1.w * b.w;
            n1 += a1.x * a1.x + a1.y * a1.y + a1.z * a1.z + a1.w * a1.w;
            qn += b.x * b.x + b.y * b.y + b.z * b.z + b.w * b.w;
        }
    } else {
        #pragma unroll
        for (int u = 0; u < 4; u++) {
            int i = tid + u * 256;
            float4 a0 = __ldcs(&m0[i]);    // evict-first DRAM stream
            float4 a1 = __ldcs(&m1[i]);
            float4 b  = qv[i];
            d0 += a0.x * b.x + a0.y * b.y + a0.z * b.z + a0.w * b.w;
            n0 += a0.x * a0.x + a0.y * a0.y + a0.z * a0.z + a0.w * a0.w;
            d1 += a1.x * b.x + a1.y * b.y + a1.z * b.z + a1.w * b.w;
            n1 += a1.x * a1.x + a1.y * a1.y + a1.z * a1.z + a1.w * a1.w;
            qn += b.x * b.x + b.y * b.y + b.z * b.z + b.w * b.w;
        }
    }

    #pragma unroll
    for (int o = 16; o > 0; o >>= 1) {
        d0 += __shfl_down_sync(0xffffffffu, d0, o);
        n0 += __shfl_down_sync(0xffffffffu, n0, o);
        d1 += __shfl_down_sync(0xffffffffu, d1, o);
        n1 += __shfl_down_sync(0xffffffffu, n1, o);
        qn += __shfl_down_sync(0xffffffffu, qn, o);
    }

    __shared__ float s0[8], s1[8], s2[8], s3[8], s4[8];
    const int w = tid >> 5;
    if ((tid & 31) == 0) { s0[w] = d0; s1[w] = n0; s2[w] = d1; s3[w] = n1; s4[w] = qn; }
    __syncthreads();

    if (tid == 0) {
        float D0 = 0.f, N0 = 0.f, D1 = 0.f, N1 = 0.f, Q = 0.f;
        #pragma unroll
        for (int i = 0; i < 8; i++) {
            D0 += s0[i]; N0 += s1[i]; D1 += s2[i]; N1 += s3[i]; Q += s4[i];
        }
        float qs = sqrtf(Q);
        float sim0 = D0 / fmaxf(qs * sqrtf(N0), 1e-8f);
        float sim1 = D1 / fmaxf(qs * sqrtf(N1), 1e-8f);
        g_weighted[r0] = sim0 * imp[r0] * expf(-0.001f * age[r0]);
        g_weighted[r1] = sim1 * imp[r1] * expf(-0.001f * age[r1]);
    }
}

// ---------------------------------------------------------------------------
// Kernel 2: top-8 of 8192 + gather/mean, fused. Single block of 1024 threads.
// ---------------------------------------------------------------------------
__global__ __launch_bounds__(1024) void topk_gather_kernel(const float* __restrict__ mb)
{
    __shared__ float w[CAP];          // 32 KB
    __shared__ float bv[32];
    __shared__ int   bi[32];
    __shared__ int   s_idx[TOPK];

    const int tid = threadIdx.x;
    for (int i = tid; i < CAP; i += 1024) w[i] = g_weighted[i];
    __syncthreads();

    for (int k = 0; k < TOPK; k++) {
        float best = -3.0e38f;
        int   idx  = -1;
        #pragma unroll
        for (int i = tid; i < CAP; i += 1024) {
            float v = w[i];
            if (v > best) { best = v; idx = i; }   // strict > keeps min index on ties
        }
        #pragma unroll
        for (int o = 16; o > 0; o >>= 1) {
            float ov = __shfl_down_sync(0xffffffffu, best, o);
            int   oi = __shfl_down_sync(0xffffffffu, idx, o);
            if (ov > best || (ov == best && oi < idx)) { best = ov; idx = oi; }
        }
        if ((tid & 31) == 0) { bv[tid >> 5] = best; bi[tid >> 5] = idx; }
        __syncthreads();
        if (tid == 0) {
            float bb = bv[0]; int ii = bi[0];
            #pragma unroll
            for (int j = 1; j < 32; j++)
                if (bv[j] > bb || (bv[j] == bb && bi[j] < ii)) { bb = bv[j]; ii = bi[j]; }
            s_idx[k] = ii;
            g_topidx[k] = ii;
            w[ii] = -3.0e38f;           // exclude from next pass
        }
        __syncthreads();
    }

    // gather: retrieved = mean of the 8 selected rows (1 float4 per thread)
    const float4* mbv = reinterpret_cast<const float4*>(mb);
    const int j = tid;                  // 0..1023 float4 lanes
    float4 acc = make_float4(0.f, 0.f, 0.f, 0.f);
    #pragma unroll
    for (int t = 0; t < TOPK; t++) {
        float4 x = __ldg(&mbv[(size_t)s_idx[t] * NV4 + j]);
        acc.x += x.x; acc.y += x.y; acc.z += x.z; acc.w += x.w;
    }
    reinterpret_cast<float4*>(g_retrieved)[j] =
        make_float4(acc.x * 0.125f, acc.y * 0.125f, acc.z * 0.125f, acc.w * 0.125f);
}

// ---------------------------------------------------------------------------
// Kernel 3: decode GEMV, 2 rows/block. W_dec default-cached -> L2-resident
// across graph replays (mb streams are policy-contained).
// ---------------------------------------------------------------------------
__global__ __launch_bounds__(256) void gemv_kernel(
    const float* __restrict__ W,
    const float* __restrict__ b,
    float* __restrict__ out)
{
    const int r0  = blockIdx.x * 2;
    const int r1  = r0 + 1;
    const int tid = threadIdx.x;
    const float4* w0 = reinterpret_cast<const float4*>(W) + (size_t)r0 * NV4;
    const float4* w1 = reinterpret_cast<const float4*>(W) + (size_t)r1 * NV4;
    const float4* rv = reinterpret_cast<const float4*>(g_retrieved);

    float a0 = 0.f, a1 = 0.f;
    #pragma unroll
    for (int u = 0; u < 4; u++) {
        int i = tid + u * 256;
        float4 x0 = __ldg(&w0[i]);
        float4 x1 = __ldg(&w1[i]);
        float4 v  = rv[i];
        a0 += x0.x * v.x + x0.y * v.y + x0.z * v.z + x0.w * v.w;
        a1 += x1.x * v.x + x1.y * v.y + x1.z * v.z + x1.w * v.w;
    }
    #pragma unroll
    for (int o = 16; o > 0; o >>= 1) {
        a0 += __shfl_down_sync(0xffffffffu, a0, o);
        a1 += __shfl_down_sync(0xffffffffu, a1, o);
    }

    __shared__ float sa[8], sb[8];
    const int w = tid >> 5;
    if ((tid & 31) == 0) { sa[w] = a0; sb[w] = a1; }
    __syncthreads();
    if (tid == 0) {
        float t0 = 0.f, t1 = 0.f;
        #pragma unroll
        for (int i = 0; i < 8; i++) { t0 += sa[i]; t1 += sb[i]; }
        out[r0] = t0 + b[r0];
        out[r1] = t1 + b[r1];
    }
}

// ---------------------------------------------------------------------------
extern "C" void kernel_launch(void* const* d_in, const int* in_sizes, int n_in,
                              void* d_out, int out_size)
{
    const float* q   = (const float*)d_in[0];  // [4096]
    const float* mb  = (const float*)d_in[1];  // [8192, 4096]
    const float* imp = (const float*)d_in[2];  // [8192]
    const float* age = (const float*)d_in[3];  // [8192]
    const float* W   = (const float*)d_in[4];  // [4096, 4096]
    const float* b   = (const float*)d_in[5];  // [4096]
    float* out = (float*)d_out;                // [4096]

    score_kernel<<<CAP / 2, 256>>>(q, mb, imp, age);
    topk_gather_kernel<<<1, 1024>>>(mb);
    gemv_kernel<<<DIM / 2, 256>>>(W, b, out);
}